// round 3
// baseline (speedup 1.0000x reference)
#include <cuda_runtime.h>
#include <cuda_bf16.h>

// R3: occupancy/latency fix. BM 64->32 (grid 512), thread tile 8x4 -> 4x4
// (acc 64->32 regs), launch_bounds(128,5). Same f32x2 K-paired GEMM core,
// same top-8 + sigmoid + L1-normalize tail.
// Output: [T*8 idx as float | T*8 weights].

#define FMA2(c, a, b) asm("fma.rn.f32x2 %0, %1, %2, %0;" : "+l"(c) : "l"(a), "l"(b))

#define TM 4
#define TN 4

__global__ __launch_bounds__(128, 5) void moe_gate_kernel(
    const float* __restrict__ X,
    const float* __restrict__ W,
    const float* __restrict__ bias,
    float* __restrict__ out,
    int w_off)
{
    // BM=32 tokens, BN=64 experts, BK=16 k, double buffered.
    __shared__ union {
        struct {
            float  As[2][32][20];   // [buf][token][k] (pad to 20 floats)
            float2 Bs[2][8][64];    // [buf][k-pair][expert]
        } mm;
        float Cs[32][65];           // logits for top-k phase (after mainloop)
    } sm;

    const int tid  = threadIdx.x;        // 0..127
    const int tx   = tid & 15;           // expert group: e0 = 4*tx
    const int ty   = tid >> 4;           // token group:  m0 = 4*ty (0..7)
    const int tok0 = blockIdx.x * 32;

    const int m0 = ty * TM;
    const int e0 = tx * TN;

    // A loader: row = tid>>2 (0..31), koff = (tid&3)*4 — one float4/thread/tile
    const int la_row = tid >> 2;
    const int la_k   = (tid & 3) * 4;
    // B loader: e = tid>>1 (0..63), koff = (tid&1)*8 — two float4/thread/tile
    const int lb_e = tid >> 1;
    const int lb_k = (tid & 1) * 8;

    const float* aP = X + (size_t)(tok0 + la_row) * 2048 + la_k;
    const float* bP = W + (size_t)lb_e * 2048 + lb_k;

    unsigned long long acc[TM][TN];
    #pragma unroll
    for (int m = 0; m < TM; ++m)
        #pragma unroll
        for (int e = 0; e < TN; ++e) acc[m][e] = 0ull;

    // ---- preload tile 0 ----
    float4 pa  = *(const float4*)aP;
    float4 pb0 = *(const float4*)bP;
    float4 pb1 = *(const float4*)(bP + 4);
    {
        *(float4*)&sm.mm.As[0][la_row][la_k] = pa;
        const int kp = lb_k >> 1;           // 0 or 4
        sm.mm.Bs[0][kp][lb_e]     = make_float2(pb0.x, pb0.y);
        sm.mm.Bs[0][kp + 1][lb_e] = make_float2(pb0.z, pb0.w);
        sm.mm.Bs[0][kp + 2][lb_e] = make_float2(pb1.x, pb1.y);
        sm.mm.Bs[0][kp + 3][lb_e] = make_float2(pb1.z, pb1.w);
    }
    __syncthreads();

    #pragma unroll 1
    for (int t = 0; t < 128; ++t) {
        const int cur = t & 1;
        if (t < 127) {                       // prefetch next tile into regs
            pa  = *(const float4*)(aP + (t + 1) * 16);
            pb0 = *(const float4*)(bP + (t + 1) * 16);
            pb1 = *(const float4*)(bP + (t + 1) * 16 + 4);
        }
        #pragma unroll
        for (int kk = 0; kk < 8; kk += 2) {
            ulonglong2 b00 = *(const ulonglong2*)(&sm.mm.Bs[cur][kk][e0]);
            ulonglong2 b01 = *(const ulonglong2*)(&sm.mm.Bs[cur][kk][e0 + 2]);
            ulonglong2 b10 = *(const ulonglong2*)(&sm.mm.Bs[cur][kk + 1][e0]);
            ulonglong2 b11 = *(const ulonglong2*)(&sm.mm.Bs[cur][kk + 1][e0 + 2]);
            #pragma unroll
            for (int m = 0; m < TM; ++m) {
                ulonglong2 a2 = *(const ulonglong2*)(&sm.mm.As[cur][m0 + m][kk * 2]);
                FMA2(acc[m][0], a2.x, b00.x);
                FMA2(acc[m][1], a2.x, b00.y);
                FMA2(acc[m][2], a2.x, b01.x);
                FMA2(acc[m][3], a2.x, b01.y);
                FMA2(acc[m][0], a2.y, b10.x);
                FMA2(acc[m][1], a2.y, b10.y);
                FMA2(acc[m][2], a2.y, b11.x);
                FMA2(acc[m][3], a2.y, b11.y);
            }
        }
        if (t < 127) {
            const int nxt = cur ^ 1;
            *(float4*)&sm.mm.As[nxt][la_row][la_k] = pa;
            const int kp = lb_k >> 1;
            sm.mm.Bs[nxt][kp][lb_e]     = make_float2(pb0.x, pb0.y);
            sm.mm.Bs[nxt][kp + 1][lb_e] = make_float2(pb0.z, pb0.w);
            sm.mm.Bs[nxt][kp + 2][lb_e] = make_float2(pb1.x, pb1.y);
            sm.mm.Bs[nxt][kp + 3][lb_e] = make_float2(pb1.z, pb1.w);
            __syncthreads();
        }
    }

    // ---- epilogue: reduce packed pairs into Cs (union overlays As/Bs) ----
    __syncthreads();   // everyone done reading As/Bs before Cs overwrites them
    #pragma unroll
    for (int m = 0; m < TM; ++m)
        #pragma unroll
        for (int e = 0; e < TN; ++e) {
            unsigned long long v = acc[m][e];
            float lo = __uint_as_float((unsigned)(v & 0xffffffffull));
            float hi = __uint_as_float((unsigned)(v >> 32));
            sm.Cs[m0 + m][e0 + e] = lo + hi;
        }
    __syncthreads();

    // ---- top-8 per token; one warp handles 8 tokens ----
    const int lane = tid & 31;
    const int warp = tid >> 5;
    const float blo = bias[lane];
    const float bhi = bias[lane + 32];
    const float NEG_INF = __int_as_float(0xff800000);

    #pragma unroll 1
    for (int tt = 0; tt < 8; ++tt) {
        const int m   = warp * 8 + tt;
        const int tok = tok0 + m;
        const float v0 = sm.Cs[m][lane];
        const float v1 = sm.Cs[m][lane + 32];
        float b0 = v0 + blo;
        float b1 = v1 + bhi;

        float sel_p = 0.0f;
        int   sel_i = 0;

        #pragma unroll
        for (int k = 0; k < 8; ++k) {
            float cv; int ci;
            if (b1 > b0) { cv = b1; ci = lane + 32; }
            else         { cv = b0; ci = lane; }
            #pragma unroll
            for (int off = 16; off; off >>= 1) {
                float ov = __shfl_down_sync(0xffffffffu, cv, off);
                int   oi = __shfl_down_sync(0xffffffffu, ci, off);
                if (ov > cv || (ov == cv && oi < ci)) { cv = ov; ci = oi; }
            }
            ci = __shfl_sync(0xffffffffu, ci, 0);
            float rawcand = (ci & 32) ? v1 : v0;        // sigmoid of UNbiased logit
            float raw = __shfl_sync(0xffffffffu, rawcand, ci & 31);
            float p = 1.0f / (1.0f + __expf(-raw));
            if (lane == k) { sel_p = p; sel_i = ci; }
            if (ci == lane)           b0 = NEG_INF;     // mask winner
            else if (ci == lane + 32) b1 = NEG_INF;
        }

        float s = sel_p;
        #pragma unroll
        for (int off = 16; off; off >>= 1) s += __shfl_xor_sync(0xffffffffu, s, off);
        s = fmaxf(s, 1e-12f);

        if (lane < 8) {
            out[(size_t)tok * 8 + lane]         = (float)sel_i;
            out[(size_t)w_off + tok * 8 + lane] = sel_p / s;
        }
    }
}

extern "C" void kernel_launch(void* const* d_in, const int* in_sizes, int n_in,
                              void* d_out, int out_size) {
    const float* X    = (const float*)d_in[0];
    const float* W    = (const float*)d_in[1];
    const float* bias = (const float*)d_in[2];
    float* out = (float*)d_out;

    const int T = in_sizes[0] / 2048;   // 16384 tokens
    const int w_off = out_size >> 1;    // weights live in the second half

    moe_gate_kernel<<<T / 32, 128>>>(X, W, bias, out, w_off);
}

// round 4
// speedup vs baseline: 1.4135x; 1.4135x over previous
#include <cuda_runtime.h>
#include <cuda_bf16.h>

// R4: crossbar fix. Warp covers all 64 experts (e0 = 2*lane) -> B reads are
// contiguous 512B/warp, conflict-free. A reads are warp-uniform broadcasts.
// 256 threads, BM=64, TM=8 tokens/warp, TN=2 experts/thread, f32x2 K-pairing.
// Output: [T*8 idx as float | T*8 weights].

#define FMA2(c, a, b) asm("fma.rn.f32x2 %0, %1, %2, %0;" : "+l"(c) : "l"(a), "l"(b))

#define TM 8

__global__ __launch_bounds__(256, 3) void moe_gate_kernel(
    const float* __restrict__ X,
    const float* __restrict__ W,
    const float* __restrict__ bias,
    float* __restrict__ out,
    int w_off)
{
    // BM=64 tokens, BN=64 experts, BK=16 k, double buffered.
    __shared__ union {
        struct {
            float  As[2][64][20];   // [buf][token][k], 80B rows
            float2 Bs[2][8][66];    // [buf][k-pair][expert], 528B rows (bank pad)
        } mm;
        float Cs[64][65];           // logits for top-k phase
    } sm;

    const int tid  = threadIdx.x;        // 0..255
    const int lane = tid & 31;
    const int warp = tid >> 5;           // 0..7
    const int tok0 = blockIdx.x * 64;

    const int m0 = warp * TM;            // 8 tokens per warp
    const int e0 = lane * 2;             // 2 experts per lane (covers all 64)

    // Loaders: one float4 per thread per tile for each of A and B.
    const int lrow = tid >> 2;           // 0..63
    const int lk   = (tid & 3) * 4;      // 0,4,8,12
    const int kp0  = (tid & 3) * 2;      // k-pair index for B store

    const float* aP = X + (size_t)(tok0 + lrow) * 2048 + lk;
    const float* bP = W + (size_t)lrow * 2048 + lk;

    unsigned long long acc[TM][2];
    #pragma unroll
    for (int m = 0; m < TM; ++m) { acc[m][0] = 0ull; acc[m][1] = 0ull; }

    // ---- preload tile 0 ----
    float4 pa = *(const float4*)aP;
    float4 pb = *(const float4*)bP;
    {
        *(float4*)&sm.mm.As[0][lrow][lk] = pa;
        sm.mm.Bs[0][kp0][lrow]     = make_float2(pb.x, pb.y);
        sm.mm.Bs[0][kp0 + 1][lrow] = make_float2(pb.z, pb.w);
    }
    __syncthreads();

    #pragma unroll 1
    for (int t = 0; t < 128; ++t) {
        const int cur = t & 1;
        if (t < 127) {                       // prefetch next tile into regs
            pa = *(const float4*)(aP + (t + 1) * 16);
            pb = *(const float4*)(bP + (t + 1) * 16);
        }
        #pragma unroll
        for (int kk = 0; kk < 8; kk += 2) {
            // B: experts e0,e0+1 for k-pairs kk and kk+1 (16B, lane-stride 16B)
            ulonglong2 b0 = *(const ulonglong2*)(&sm.mm.Bs[cur][kk][e0]);
            ulonglong2 b1 = *(const ulonglong2*)(&sm.mm.Bs[cur][kk + 1][e0]);
            #pragma unroll
            for (int m = 0; m < TM; ++m) {
                // A: k floats 2kk..2kk+3 for token m0+m (warp-uniform broadcast)
                ulonglong2 a2 = *(const ulonglong2*)(&sm.mm.As[cur][m0 + m][kk * 2]);
                FMA2(acc[m][0], a2.x, b0.x);
                FMA2(acc[m][1], a2.x, b0.y);
                FMA2(acc[m][0], a2.y, b1.x);
                FMA2(acc[m][1], a2.y, b1.y);
            }
        }
        if (t < 127) {
            const int nxt = cur ^ 1;
            *(float4*)&sm.mm.As[nxt][lrow][lk] = pa;
            sm.mm.Bs[nxt][kp0][lrow]     = make_float2(pb.x, pb.y);
            sm.mm.Bs[nxt][kp0 + 1][lrow] = make_float2(pb.z, pb.w);
            __syncthreads();
        }
    }

    // ---- epilogue: reduce packed pairs into Cs (union overlays As/Bs) ----
    __syncthreads();   // all reads of As/Bs done before Cs overwrites
    #pragma unroll
    for (int m = 0; m < TM; ++m) {
        #pragma unroll
        for (int e = 0; e < 2; ++e) {
            unsigned long long v = acc[m][e];
            float lo = __uint_as_float((unsigned)(v & 0xffffffffull));
            float hi = __uint_as_float((unsigned)(v >> 32));
            sm.Cs[m0 + m][e0 + e] = lo + hi;
        }
    }
    __syncthreads();

    // ---- top-8 per token; each warp handles its own 8 tokens ----
    const float blo = bias[lane];
    const float bhi = bias[lane + 32];
    const float NEG_INF = __int_as_float(0xff800000);

    #pragma unroll 1
    for (int tt = 0; tt < TM; ++tt) {
        const int m   = m0 + tt;
        const int tok = tok0 + m;
        const float v0 = sm.Cs[m][lane];
        const float v1 = sm.Cs[m][lane + 32];
        float b0 = v0 + blo;
        float b1 = v1 + bhi;

        float sel_p = 0.0f;
        int   sel_i = 0;

        #pragma unroll
        for (int k = 0; k < 8; ++k) {
            float cv; int ci;
            if (b1 > b0) { cv = b1; ci = lane + 32; }
            else         { cv = b0; ci = lane; }
            #pragma unroll
            for (int off = 16; off; off >>= 1) {
                float ov = __shfl_down_sync(0xffffffffu, cv, off);
                int   oi = __shfl_down_sync(0xffffffffu, ci, off);
                if (ov > cv || (ov == cv && oi < ci)) { cv = ov; ci = oi; }
            }
            ci = __shfl_sync(0xffffffffu, ci, 0);
            float rawcand = (ci & 32) ? v1 : v0;        // sigmoid of UNbiased logit
            float raw = __shfl_sync(0xffffffffu, rawcand, ci & 31);
            float p = 1.0f / (1.0f + __expf(-raw));
            if (lane == k) { sel_p = p; sel_i = ci; }
            if (ci == lane)           b0 = NEG_INF;     // mask winner
            else if (ci == lane + 32) b1 = NEG_INF;
        }

        float s = sel_p;
        #pragma unroll
        for (int off = 16; off; off >>= 1) s += __shfl_xor_sync(0xffffffffu, s, off);
        s = fmaxf(s, 1e-12f);

        if (lane < 8) {
            out[(size_t)tok * 8 + lane]         = (float)sel_i;
            out[(size_t)w_off + tok * 8 + lane] = sel_p / s;
        }
    }
}

extern "C" void kernel_launch(void* const* d_in, const int* in_sizes, int n_in,
                              void* d_out, int out_size) {
    const float* X    = (const float*)d_in[0];
    const float* W    = (const float*)d_in[1];
    const float* bias = (const float*)d_in[2];
    float* out = (float*)d_out;

    const int T = in_sizes[0] / 2048;   // 16384 tokens
    const int w_off = out_size >> 1;    // weights in second half

    moe_gate_kernel<<<T / 64, 256>>>(X, W, bias, out, w_off);
}

// round 5
// speedup vs baseline: 1.4451x; 1.0224x over previous
#include <cuda_runtime.h>
#include <cuda_bf16.h>

// R5: wavefront-economy GEMM. 4x8 lane grid, 4 tok x 4 exp per lane, f32x2
// K-pairing. A reads: 1 wf per LDS.128 (4x16B distinct). B reads: 128B-block
// physical expert layout -> each LDS.128 covers exactly one 128B line.
// Top-8 via REDUX (reduce_max/min) on monotone-uint biased logits.
// Output: [T*8 idx as float | T*8 weights].

#define FMA2(c, a, b) asm("fma.rn.f32x2 %0, %1, %2, %0;" : "+l"(c) : "l"(a), "l"(b))

__global__ __launch_bounds__(256, 2) void moe_gate_kernel(
    const float* __restrict__ X,
    const float* __restrict__ W,
    const float* __restrict__ bias,
    float* __restrict__ out,
    int w_off)
{
    // BM=64 tokens, BN=64 experts, BK=16 k, double buffered.
    __shared__ union {
        struct {
            float  As[2][64][20];   // [buf][token][k], 80B rows
            float2 Bs[2][8][64];    // [buf][kpair][phys expert entry], 512B rows
        } mm;
        float Cs[64][65];           // raw logits for top-k phase
    } sm;

    const int tid  = threadIdx.x;        // 0..255
    const int lane = tid & 31;
    const int warp = tid >> 5;           // 0..7
    const int tok0 = blockIdx.x * 64;

    const int wr = warp >> 1;            // warp row 0..3 (16 tokens each)
    const int wc = warp & 1;             // warp col 0..1 (32 experts each)
    const int wy = lane >> 3;            // 0..3
    const int wx = lane & 7;             // 0..7

    // tokens: m(j) = wr*16 + wy + 4j ; experts: e(i) = wc*32 + wx*4 + i
    const int mbase = wr * 16 + wy;
    const int ebase = wc * 32 + wx * 4;

    // Loaders: one float4 per thread per tile for each of A and B.
    const int lrow = tid >> 2;           // 0..63 (token for A / expert for B)
    const int lk   = (tid & 3) * 4;      // 0,4,8,12
    const int kp0  = (tid & 3) * 2;      // kpair index for B store
    // physical B entry for expert lrow (f32x2 units within a kpair row)
    const int eL   = lrow & 31;
    const int bent = (lrow >> 5) * 32 + ((eL & 2) ? 16 : 0) + ((eL >> 2) << 1) + (eL & 1);

    const float* aP = X + (size_t)(tok0 + lrow) * 2048 + lk;
    const float* bP = W + (size_t)lrow * 2048 + lk;

    unsigned long long acc[4][4];
    #pragma unroll
    for (int j = 0; j < 4; ++j)
        #pragma unroll
        for (int i = 0; i < 4; ++i) acc[j][i] = 0ull;

    // ---- preload tile 0 ----
    float4 pa = *(const float4*)aP;
    float4 pb = *(const float4*)bP;
    {
        *(float4*)&sm.mm.As[0][lrow][lk] = pa;
        sm.mm.Bs[0][kp0][bent]     = make_float2(pb.x, pb.y);
        sm.mm.Bs[0][kp0 + 1][bent] = make_float2(pb.z, pb.w);
    }
    __syncthreads();

    const int bRead = wc * 32 + wx * 2;  // first f32x2 entry this lane reads

    #pragma unroll 1
    for (int t = 0; t < 128; ++t) {
        const int cur = t & 1;
        if (t < 127) {                   // prefetch next tile into regs
            pa = *(const float4*)(aP + (t + 1) * 16);
            pb = *(const float4*)(bP + (t + 1) * 16);
        }
        #pragma unroll
        for (int kk = 0; kk < 8; kk += 2) {
            // B: experts ebase..ebase+3 for kpairs kk, kk+1 (each load = one 128B line)
            ulonglong2 b0a = *(const ulonglong2*)(&sm.mm.Bs[cur][kk][bRead]);
            ulonglong2 b0b = *(const ulonglong2*)(&sm.mm.Bs[cur][kk][bRead + 16]);
            ulonglong2 b1a = *(const ulonglong2*)(&sm.mm.Bs[cur][kk + 1][bRead]);
            ulonglong2 b1b = *(const ulonglong2*)(&sm.mm.Bs[cur][kk + 1][bRead + 16]);
            #pragma unroll
            for (int j = 0; j < 4; ++j) {
                ulonglong2 a2 = *(const ulonglong2*)(&sm.mm.As[cur][mbase + 4 * j][kk * 2]);
                FMA2(acc[j][0], a2.x, b0a.x);
                FMA2(acc[j][1], a2.x, b0a.y);
                FMA2(acc[j][2], a2.x, b0b.x);
                FMA2(acc[j][3], a2.x, b0b.y);
                FMA2(acc[j][0], a2.y, b1a.x);
                FMA2(acc[j][1], a2.y, b1a.y);
                FMA2(acc[j][2], a2.y, b1b.x);
                FMA2(acc[j][3], a2.y, b1b.y);
            }
        }
        if (t < 127) {
            const int nxt = cur ^ 1;
            *(float4*)&sm.mm.As[nxt][lrow][lk] = pa;
            sm.mm.Bs[nxt][kp0][bent]     = make_float2(pb.x, pb.y);
            sm.mm.Bs[nxt][kp0 + 1][bent] = make_float2(pb.z, pb.w);
            __syncthreads();
        }
    }

    // ---- epilogue: reduce packed pairs into Cs (union overlays As/Bs) ----
    __syncthreads();   // all As/Bs reads done before Cs overwrites
    #pragma unroll
    for (int j = 0; j < 4; ++j)
        #pragma unroll
        for (int i = 0; i < 4; ++i) {
            unsigned long long v = acc[j][i];
            float lo = __uint_as_float((unsigned)(v & 0xffffffffull));
            float hi = __uint_as_float((unsigned)(v >> 32));
            sm.Cs[mbase + 4 * j][ebase + i] = lo + hi;
        }
    __syncthreads();

    // ---- top-8 per token via REDUX; warp handles 8 tokens ----
    const float blo = bias[lane];
    const float bhi = bias[lane + 32];

    #pragma unroll 1
    for (int tt = 0; tt < 8; ++tt) {
        const int m   = warp * 8 + tt;
        const int tok = tok0 + m;
        const float v0 = sm.Cs[m][lane];
        const float v1 = sm.Cs[m][lane + 32];
        // monotone uint transform of biased logits (order-preserving)
        unsigned c0 = __float_as_uint(v0 + blo);
        unsigned c1 = __float_as_uint(v1 + bhi);
        unsigned u0 = c0 ^ (((int)c0 >> 31) | 0x80000000u);
        unsigned u1 = c1 ^ (((int)c1 >> 31) | 0x80000000u);

        int sel_i = 0;
        #pragma unroll
        for (int k = 0; k < 8; ++k) {
            unsigned cu; int ci;
            if (u1 > u0) { cu = u1; ci = lane + 32; }
            else         { cu = u0; ci = lane; }
            unsigned mx = __reduce_max_sync(0xffffffffu, cu);
            unsigned cand = (cu == mx) ? (unsigned)ci : 1000u;
            int wi = (int)__reduce_min_sync(0xffffffffu, cand);
            if (lane == k) sel_i = wi;
            if (wi < 32) { if (lane == wi)      u0 = 0u; }
            else         { if (lane == wi - 32) u1 = 0u; }
        }

        // sigmoid of raw logits + L1 normalize, in parallel over the 8 winners
        float p = 0.0f;
        if (lane < 8) {
            float raw = sm.Cs[m][sel_i];
            p = 1.0f / (1.0f + __expf(-raw));
        }
        float s = p;
        #pragma unroll
        for (int off = 4; off; off >>= 1) s += __shfl_xor_sync(0xffffffffu, s, off);
        s = fmaxf(s, 1e-12f);

        if (lane < 8) {
            out[(size_t)tok * 8 + lane]         = (float)sel_i;
            out[(size_t)w_off + tok * 8 + lane] = p / s;
        }
    }
}

extern "C" void kernel_launch(void* const* d_in, const int* in_sizes, int n_in,
                              void* d_out, int out_size) {
    const float* X    = (const float*)d_in[0];
    const float* W    = (const float*)d_in[1];
    const float* bias = (const float*)d_in[2];
    float* out = (float*)d_out;

    const int T = in_sizes[0] / 2048;   // 16384 tokens
    const int w_off = out_size >> 1;    // weights in second half

    moe_gate_kernel<<<T / 64, 256>>>(X, W, bias, out, w_off);
}

// round 8
// speedup vs baseline: 2.3661x; 1.6373x over previous
#include <cuda_runtime.h>
#include <cuda_bf16.h>
#include <cstdint>

// R8: HMMA path with flip-proof accumulation. 3-term bf16 split (6 combos).
// Main term a1*b1 -> per-chunk partial, Fast2Sum-folded (compensated) into s.
// Correction terms -> separate small-scale mma accumulator cr (also holds the
// fold residues). Logit error ~3e-7 (== FFMA level that passed). W pre-split
// once into __device__ scratch. CTA: 64 tok x 64 exp, BK=32, double-buffered.
// Output: [T*8 idx as float | T*8 weights].

#define LDSM4(r0, r1, r2, r3, addr)                                           \
    asm volatile("ldmatrix.sync.aligned.m8n8.x4.shared.b16 {%0,%1,%2,%3}, [%4];" \
                 : "=r"(r0), "=r"(r1), "=r"(r2), "=r"(r3) : "r"(addr))

#define MMA16816(d, a, b0, b1)                                                \
    asm volatile("mma.sync.aligned.m16n8k16.row.col.f32.bf16.bf16.f32 "       \
                 "{%0,%1,%2,%3}, {%4,%5,%6,%7}, {%8,%9}, {%0,%1,%2,%3};"      \
                 : "+f"((d)[0]), "+f"((d)[1]), "+f"((d)[2]), "+f"((d)[3])     \
                 : "r"((a)[0]), "r"((a)[1]), "r"((a)[2]), "r"((a)[3]),        \
                   "r"(b0), "r"(b1))

// Pre-split W scratch: 3 bf16 terms, [term][expert*2048 + k]
__device__ __align__(16) __nv_bfloat16 g_Wsplit[3][64 * 2048];

static __device__ __forceinline__ void split8(float4 v0, float4 v1,
                                              uint4& o0, uint4& o1, uint4& o2) {
    float f[8] = {v0.x, v0.y, v0.z, v0.w, v1.x, v1.y, v1.z, v1.w};
    unsigned short a[8], b[8], c[8];
    #pragma unroll
    for (int j = 0; j < 8; ++j) {
        __nv_bfloat16 t1 = __float2bfloat16(f[j]);
        float r1 = f[j] - __bfloat162float(t1);
        __nv_bfloat16 t2 = __float2bfloat16(r1);
        float r2 = r1 - __bfloat162float(t2);
        __nv_bfloat16 t3 = __float2bfloat16(r2);
        a[j] = __bfloat16_as_ushort(t1);
        b[j] = __bfloat16_as_ushort(t2);
        c[j] = __bfloat16_as_ushort(t3);
    }
    o0 = make_uint4(a[0] | ((unsigned)a[1] << 16), a[2] | ((unsigned)a[3] << 16),
                    a[4] | ((unsigned)a[5] << 16), a[6] | ((unsigned)a[7] << 16));
    o1 = make_uint4(b[0] | ((unsigned)b[1] << 16), b[2] | ((unsigned)b[3] << 16),
                    b[4] | ((unsigned)b[5] << 16), b[6] | ((unsigned)b[7] << 16));
    o2 = make_uint4(c[0] | ((unsigned)c[1] << 16), c[2] | ((unsigned)c[3] << 16),
                    c[4] | ((unsigned)c[5] << 16), c[6] | ((unsigned)c[7] << 16));
}

__global__ void w_split_kernel(const float* __restrict__ W) {
    int i = (blockIdx.x * 256 + threadIdx.x) * 8;     // 64 blocks cover 131072
    float4 v0 = *(const float4*)(W + i);
    float4 v1 = *(const float4*)(W + i + 4);
    uint4 o0, o1, o2;
    split8(v0, v1, o0, o1, o2);
    *(uint4*)(&g_Wsplit[0][i]) = o0;
    *(uint4*)(&g_Wsplit[1][i]) = o1;
    *(uint4*)(&g_Wsplit[2][i]) = o2;
}

// smem layout (dynamic, 61440 B):
//   A tiles: [buf][term][64 rows][40 bf16]  at 0      (stride/buf-term 5120 B)
//   B tiles: same shape                      at 30720
//   Cs float[64][65] overlays A region in the epilogue.
#define TILE_BT 5120
#define B_BASE  30720

extern __shared__ char smem[];

__global__ __launch_bounds__(256, 2) void moe_gate_mma(
    const float* __restrict__ X,
    const float* __restrict__ bias,
    float* __restrict__ out,
    int w_off)
{
    const int tid  = threadIdx.x;
    const int lane = tid & 31;
    const int wid  = tid >> 5;
    const int wr   = wid >> 1;           // warp row 0..3 (16 tokens)
    const int wc   = wid & 1;            // warp col 0..1 (32 experts)
    const int tok0 = blockIdx.x * 64;

    uint32_t sb;
    asm("{ .reg .u64 t; cvta.to.shared.u64 t, %1; cvt.u32.u64 %0, t; }"
        : "=r"(sb) : "l"(smem));

    // -- gmem loader mapping: row = tid>>2 (0..63), kgroup = tid&3 (8 k each) --
    const int lrow = tid >> 2;
    const int lkg  = tid & 3;
    const float* aP = X + (size_t)(tok0 + lrow) * 2048 + lkg * 8;
    const __nv_bfloat16* wP = &g_Wsplit[0][0] + lrow * 2048 + lkg * 8;
    const int stO = lrow * 80 + lkg * 16;          // byte offset within a tile

    // -- ldmatrix lane offsets (bytes within a tile) --
    const int grp  = lane >> 3;
    const int a_off = (16 * wr + (lane & 7) + ((lane >> 3) & 1) * 8) * 80
                      + ((lane >> 4) & 1) * 16;
    const int b_off = (32 * wc + 8 * (grp >> 1) + (lane & 7)) * 80
                      + (grp & 1) * 16;            // +1280B for the next n-tile pair

    // Accumulators: s = compensated main sum, cr = corrections + fold residues,
    // dm = per-chunk main partial.
    float s_[4][4], cr[4][4], dm[4][4];
    #pragma unroll
    for (int nt = 0; nt < 4; ++nt)
        #pragma unroll
        for (int i = 0; i < 4; ++i) { s_[nt][i] = 0.0f; cr[nt][i] = 0.0f; }

    // ---- chunk 0: load, convert, store buf 0 ----
    float4 pa0 = *(const float4*)aP;
    float4 pa1 = *(const float4*)(aP + 4);
    uint4 pb0 = *(const uint4*)(wP);
    uint4 pb1 = *(const uint4*)(wP + 131072);
    uint4 pb2 = *(const uint4*)(wP + 262144);
    {
        uint4 o0, o1, o2;
        split8(pa0, pa1, o0, o1, o2);
        *(uint4*)(smem + 0 * TILE_BT + stO) = o0;
        *(uint4*)(smem + 1 * TILE_BT + stO) = o1;
        *(uint4*)(smem + 2 * TILE_BT + stO) = o2;
        *(uint4*)(smem + B_BASE + 0 * TILE_BT + stO) = pb0;
        *(uint4*)(smem + B_BASE + 1 * TILE_BT + stO) = pb1;
        *(uint4*)(smem + B_BASE + 2 * TILE_BT + stO) = pb2;
    }
    __syncthreads();

    #pragma unroll 1
    for (int c = 0; c < 64; ++c) {
        const int cur = c & 1;
        if (c < 63) {                                 // prefetch next chunk
            const int o = (c + 1) * 32;
            pa0 = *(const float4*)(aP + o);
            pa1 = *(const float4*)(aP + o + 4);
            pb0 = *(const uint4*)(wP + o);
            pb1 = *(const uint4*)(wP + o + 131072);
            pb2 = *(const uint4*)(wP + o + 262144);
        }
        // zero the per-chunk main partial
        #pragma unroll
        for (int nt = 0; nt < 4; ++nt)
            #pragma unroll
            for (int i = 0; i < 4; ++i) dm[nt][i] = 0.0f;

        // ---- MMA on buf cur: 2 k16-steps ----
        #pragma unroll
        for (int ks = 0; ks < 2; ++ks) {
            uint32_t af[3][4];
            #pragma unroll
            for (int sa = 0; sa < 3; ++sa)
                LDSM4(af[sa][0], af[sa][1], af[sa][2], af[sa][3],
                      sb + (cur * 3 + sa) * TILE_BT + a_off + ks * 32);
            #pragma unroll
            for (int t = 0; t < 3; ++t) {            // B term index
                uint32_t base = sb + B_BASE + (cur * 3 + t) * TILE_BT + b_off + ks * 32;
                uint32_t b0, b1, b2, b3, b4, b5, b6, b7;
                LDSM4(b0, b1, b2, b3, base);
                LDSM4(b4, b5, b6, b7, base + 1280);
                #pragma unroll
                for (int sa = 0; sa < 3; ++sa) {
                    if (sa + t < 3) {                // combos with sa+t<=2
                        if (sa == 0 && t == 0) {     // main term -> chunk partial
                            MMA16816(dm[0], af[0], b0, b1);
                            MMA16816(dm[1], af[0], b2, b3);
                            MMA16816(dm[2], af[0], b4, b5);
                            MMA16816(dm[3], af[0], b6, b7);
                        } else {                     // corrections -> cr
                            MMA16816(cr[0], af[sa], b0, b1);
                            MMA16816(cr[1], af[sa], b2, b3);
                            MMA16816(cr[2], af[sa], b4, b5);
                            MMA16816(cr[3], af[sa], b6, b7);
                        }
                    }
                }
            }
        }
        // ---- Fast2Sum fold of the chunk partial into (s_, cr) ----
        #pragma unroll
        for (int nt = 0; nt < 4; ++nt)
            #pragma unroll
            for (int i = 0; i < 4; ++i) {
                float p  = dm[nt][i];
                float t1 = s_[nt][i] + p;
                float z  = t1 - s_[nt][i];
                float e  = p - z;
                cr[nt][i] += e;
                s_[nt][i] = t1;
            }

        if (c < 63) {                                 // convert + store buf nxt
            const int nb = (cur ^ 1) * 3;
            uint4 o0, o1, o2;
            split8(pa0, pa1, o0, o1, o2);
            *(uint4*)(smem + (nb + 0) * TILE_BT + stO) = o0;
            *(uint4*)(smem + (nb + 1) * TILE_BT + stO) = o1;
            *(uint4*)(smem + (nb + 2) * TILE_BT + stO) = o2;
            *(uint4*)(smem + B_BASE + (nb + 0) * TILE_BT + stO) = pb0;
            *(uint4*)(smem + B_BASE + (nb + 1) * TILE_BT + stO) = pb1;
            *(uint4*)(smem + B_BASE + (nb + 2) * TILE_BT + stO) = pb2;
        }
        __syncthreads();
    }

    // ---- epilogue: logits -> Cs (overlays A region; mainloop ended w/ sync) ----
    float (*Cs)[65] = (float(*)[65])smem;
    {
        const int g  = lane >> 2;
        const int t2 = (lane & 3) * 2;
        #pragma unroll
        for (int nt = 0; nt < 4; ++nt) {
            const int r  = 16 * wr + g;
            const int c0 = 32 * wc + nt * 8 + t2;
            Cs[r][c0]         = s_[nt][0] + cr[nt][0];
            Cs[r][c0 + 1]     = s_[nt][1] + cr[nt][1];
            Cs[r + 8][c0]     = s_[nt][2] + cr[nt][2];
            Cs[r + 8][c0 + 1] = s_[nt][3] + cr[nt][3];
        }
    }
    __syncthreads();

    // ---- top-8 per token via REDUX; warp handles 8 tokens (R5-proven tail) ----
    const float blo = bias[lane];
    const float bhi = bias[lane + 32];

    #pragma unroll 1
    for (int tt = 0; tt < 8; ++tt) {
        const int m   = wid * 8 + tt;
        const int tok = tok0 + m;
        const float v0 = Cs[m][lane];
        const float v1 = Cs[m][lane + 32];
        unsigned c0 = __float_as_uint(v0 + blo);
        unsigned c1 = __float_as_uint(v1 + bhi);
        unsigned u0 = c0 ^ (((int)c0 >> 31) | 0x80000000u);
        unsigned u1 = c1 ^ (((int)c1 >> 31) | 0x80000000u);

        int sel_i = 0;
        #pragma unroll
        for (int k = 0; k < 8; ++k) {
            unsigned cu; int ci;
            if (u1 > u0) { cu = u1; ci = lane + 32; }
            else         { cu = u0; ci = lane; }
            unsigned mx = __reduce_max_sync(0xffffffffu, cu);
            unsigned cand = (cu == mx) ? (unsigned)ci : 1000u;
            int wi = (int)__reduce_min_sync(0xffffffffu, cand);
            if (lane == k) sel_i = wi;
            if (wi < 32) { if (lane == wi)      u0 = 0u; }
            else         { if (lane == wi - 32) u1 = 0u; }
        }

        float p = 0.0f;
        if (lane < 8) {
            float raw = Cs[m][sel_i];
            p = 1.0f / (1.0f + __expf(-raw));
        }
        float s = p;
        #pragma unroll
        for (int off = 4; off; off >>= 1) s += __shfl_xor_sync(0xffffffffu, s, off);
        s = fmaxf(s, 1e-12f);

        if (lane < 8) {
            out[(size_t)tok * 8 + lane]         = (float)sel_i;
            out[(size_t)w_off + tok * 8 + lane] = p / s;
        }
    }
}

extern "C" void kernel_launch(void* const* d_in, const int* in_sizes, int n_in,
                              void* d_out, int out_size) {
    const float* X    = (const float*)d_in[0];
    const float* W    = (const float*)d_in[1];
    const float* bias = (const float*)d_in[2];
    float* out = (float*)d_out;

    const int T = in_sizes[0] / 2048;   // 16384 tokens
    const int w_off = out_size >> 1;

    w_split_kernel<<<64, 256>>>(W);

    static bool attr_set = false;       // one-time attribute set (work unchanged)
    if (!attr_set) {
        cudaFuncSetAttribute(moe_gate_mma,
                             cudaFuncAttributeMaxDynamicSharedMemorySize, 61440);
        attr_set = true;
    }
    moe_gate_mma<<<T / 64, 256, 61440>>>(X, bias, out, w_off);
}